// round 5
// baseline (speedup 1.0000x reference)
#include <cuda_runtime.h>
#include <math.h>

#define NQ    14
#define DIM   16384
#define NT    10
#define BATCH 2048
#define NTHR  1024
#define ZZN   8192
// dyn smem: buf4 (8192 * 16B = 128KB) + zz (8192 * 8B = 64KB) = 192KB
#define DYN_SMEM (ZZN * 16 + ZZN * 8)

typedef unsigned long long u64;

__device__ float g_const[48];

// ---- packed f32x2 helpers ----
__device__ __forceinline__ u64 f2mul(u64 a, u64 b) {
    u64 r; asm("mul.rn.f32x2 %0,%1,%2;" : "=l"(r) : "l"(a), "l"(b)); return r;
}
__device__ __forceinline__ u64 f2fma(u64 a, u64 b, u64 c) {
    u64 r; asm("fma.rn.f32x2 %0,%1,%2,%3;" : "=l"(r) : "l"(a), "l"(b), "l"(c)); return r;
}
__device__ __forceinline__ u64 pk(float lo, float hi) {
    u64 r; asm("mov.b64 %0,{%1,%2};" : "=l"(r) : "f"(lo), "f"(hi)); return r;
}
__device__ __forceinline__ float2 up(u64 d) {
    float lo, hi; asm("mov.b64 {%0,%1},%2;" : "=f"(lo), "=f"(hi) : "l"(d));
    return make_float2(lo, hi);
}
__device__ __forceinline__ u64 f2neg(u64 a) { return a ^ 0x8000000080000000ULL; }
__device__ __forceinline__ u64 f2swap(u64 a) { float2 t = up(a); return pk(t.y, t.x); }
__device__ __forceinline__ u64 shflx(u64 v, int m) { return __shfl_xor_sync(0xffffffffu, v, m); }

// transpose-buffer swizzle (16B units): conflict-free for both layouts
__device__ __forceinline__ int swz13(int m) { return m ^ ((m >> 3) & 7) ^ ((m >> 10) & 7); }

// ZZ-table scramble: GF(2)-linear, bank bits injective in both layouts
__device__ __forceinline__ int sigma13(int gm) {
    return ((gm >> 3) & 1)
         | (((gm >> 4) & 1) << 1)
         | ((((gm >> 5) ^ (gm >> 11)) & 1) << 2)
         | ((((gm >> 6) ^ (gm >> 12)) & 1) << 3)
         | ((gm & 7) << 4)
         | (((gm >> 7) & 0xF) << 7)
         | (((gm >> 11) & 3) << 11);
}

// ---- gate primitives on 8 packed pairs ----
__device__ __forceinline__ void rx_local(u64* X, u64* Y, int j, u64 c2, u64 s2, u64 ns2) {
    #pragma unroll
    for (int pr = 0; pr < 8; pr++) if (!(pr & (1 << j))) {
        int e1 = pr | (1 << j);
        u64 Xa = X[pr], Ya = Y[pr], Xb = X[e1], Yb = Y[e1];
        X[pr] = f2fma(c2, Xa, f2mul(s2, Yb));
        Y[pr] = f2fma(c2, Ya, f2mul(ns2, Xb));
        X[e1] = f2fma(c2, Xb, f2mul(s2, Ya));
        Y[e1] = f2fma(c2, Yb, f2mul(ns2, Xa));
    }
}
__device__ __forceinline__ void rx_pack(u64* X, u64* Y, u64 c2, u64 s2, u64 ns2) {
    #pragma unroll
    for (int pr = 0; pr < 8; pr++) {
        u64 Xs = f2swap(X[pr]), Ys = f2swap(Y[pr]);
        X[pr] = f2fma(c2, X[pr], f2mul(s2, Ys));
        Y[pr] = f2fma(c2, Y[pr], f2mul(ns2, Xs));
    }
}
__device__ __forceinline__ void rx_shfl(u64* X, u64* Y, int msk, u64 c2, u64 s2, u64 ns2) {
    #pragma unroll
    for (int pr = 0; pr < 8; pr++) {
        u64 Xo = shflx(X[pr], msk), Yo = shflx(Y[pr], msk);
        X[pr] = f2fma(c2, X[pr], f2mul(s2, Yo));
        Y[pr] = f2fma(c2, Y[pr], f2mul(ns2, Xo));
    }
}
__device__ __forceinline__ void zz_apply(u64* X, u64* Y, const float2* zz,
                                         int base, const int* D, int hiXor) {
    #pragma unroll
    for (int pr = 0; pr < 8; pr++) {
        int i = base ^ D[pr];
        float2 fl = zz[i], fh = zz[i ^ hiXor];
        u64 FX = pk(fl.x, fh.x), FY = pk(fl.y, fh.y);
        u64 Xo = X[pr], Yo = Y[pr];
        X[pr] = f2fma(FX, Xo, f2neg(f2mul(FY, Yo)));
        Y[pr] = f2fma(FX, Yo, f2mul(FY, Xo));
    }
}

// Layout A: k[2:0]=reg pr, k3=pack, k[8:4]=lane, k[13:9]=warp  (gates q0-q8)
// Layout B: pr = k9 | k10<<1 | k0<<2, pack=k11,
//           lane = {k12,k13,k4,k5,k6}, warp = {k7,k8,k1,k2,k3} (gates q9-q13, q4-q6)

__global__ __launch_bounds__(NTHR, 1)
void evolve_kernel(const float* __restrict__ J, const float* __restrict__ g)
{
    extern __shared__ char dynraw[];
    float4* buf4 = (float4*)dynraw;                // 8192 x 16B state transpose buffer
    float2* zz   = (float2*)(dynraw + ZZN * 16);   // 8192 diagonal factors (scrambled)

    __shared__ float2 rxcs[16];
    __shared__ float  Jsh[16];
    __shared__ float  warpacc[42 * 32];

    const int t    = threadIdx.x;
    const int lane = t & 31;
    const int wrp  = t >> 5;
    const float dt = 1.0f / (float)NT;

    if (t < NQ) {
        float h = 0.5f * g[t] * dt;
        float s, c; __sincosf(h, &s, &c);
        rxcs[t] = make_float2(c, s);
    }
    if (t < NQ - 1) Jsh[t] = J[t];
    __syncthreads();

    // ZZ table: mask m (13 Gray bits), D = sum J_i (1-2 m_i), store exp(-0.5 i dt D) at sigma(m)
    for (int m = t; m < ZZN; m += NTHR) {
        float D = 0.f;
        #pragma unroll
        for (int i = 0; i < NQ - 1; i++) {
            float Ji = Jsh[i];
            D += ((m >> i) & 1) ? -Ji : Ji;
        }
        float ang = -0.5f * dt * D;
        float s, c; __sincosf(ang, &s, &c);
        zz[sigma13(m)] = make_float2(c, s);
    }
    __syncthreads();

    u64 X[8], Y[8];
    #pragma unroll
    for (int pr = 0; pr < 8; pr++) { X[pr] = pk(0.0078125f, 0.0078125f); Y[pr] = 0ULL; }

    // ZZ per-pair constexpr deltas + base indices
    const int DZA[8] = {0x00, 0x10, 0x30, 0x20, 0x60, 0x70, 0x50, 0x40};   // sigma(gray(pr))
    const int DZB[8] = {0x000, 0x300, 0x600, 0x500, 0x010, 0x310, 0x610, 0x510};
    const int kA = t << 4;
    const int idxA = sigma13((kA ^ (kA >> 1)) & 0x1FFF);
    // B thread->m base: m_i = k_{i+1}
    const int mB = ((t >> 7) & 7) | (((t >> 2) & 7) << 3) | (((t >> 5) & 3) << 6)
                 | ((t & 3) << 11);
    const int kB = mB << 1;
    const int idxB = sigma13((kB ^ (kB >> 1)) & 0x1FFF);

    #define RXC(q, C2, S2, NS2) \
        { float2 _cs = rxcs[q]; C2 = pk(_cs.x, _cs.x); S2 = pk(_cs.y, _cs.y); NS2 = f2neg(S2); }

    for (int ts = 0; ts < NT; ts += 2) {
        u64 c2, s2, ns2;
        // ======== step ts (layout A start) ========
        zz_apply(X, Y, zz, idxA, DZA, 0x41);
        RXC(0, c2, s2, ns2); rx_local(X, Y, 0, c2, s2, ns2);
        RXC(1, c2, s2, ns2); rx_local(X, Y, 1, c2, s2, ns2);
        RXC(2, c2, s2, ns2); rx_local(X, Y, 2, c2, s2, ns2);
        RXC(3, c2, s2, ns2); rx_pack(X, Y, c2, s2, ns2);
        RXC(4, c2, s2, ns2); rx_shfl(X, Y, 1,  c2, s2, ns2);
        RXC(5, c2, s2, ns2); rx_shfl(X, Y, 2,  c2, s2, ns2);
        RXC(6, c2, s2, ns2); rx_shfl(X, Y, 4,  c2, s2, ns2);
        RXC(7, c2, s2, ns2); rx_shfl(X, Y, 8,  c2, s2, ns2);
        RXC(8, c2, s2, ns2); rx_shfl(X, Y, 16, c2, s2, ns2);
        // ---- transpose A -> B ----
        __syncthreads();
        #pragma unroll
        for (int h = 0; h < 2; h++)
        #pragma unroll
        for (int pq = 0; pq < 4; pq++) {
            int p = 2 * pq;
            float2 xa = up(X[p]), ya = up(Y[p]), xb = up(X[p + 1]), yb = up(Y[p + 1]);
            float4 v = h ? make_float4(xa.y, ya.y, xb.y, yb.y)
                         : make_float4(xa.x, ya.x, xb.x, yb.x);
            buf4[swz13((t << 3) | (h << 2) | pq)] = v;
        }
        __syncthreads();
        #pragma unroll
        for (int p1 = 0; p1 < 2; p1++)
        #pragma unroll
        for (int p0 = 0; p0 < 2; p0++) {
            int m0 = mB | (p0 << 8) | (p1 << 9);
            float4 v0 = buf4[swz13(m0)];
            float4 v1 = buf4[swz13(m0 | (1 << 10))];
            int prl = p0 | (p1 << 1), prh = prl | 4;
            X[prl] = pk(v0.x, v1.x); Y[prl] = pk(v0.y, v1.y);
            X[prh] = pk(v0.z, v1.z); Y[prh] = pk(v0.w, v1.w);
        }
        RXC(9,  c2, s2, ns2); rx_local(X, Y, 0, c2, s2, ns2);
        RXC(10, c2, s2, ns2); rx_local(X, Y, 1, c2, s2, ns2);
        RXC(11, c2, s2, ns2); rx_pack(X, Y, c2, s2, ns2);
        RXC(12, c2, s2, ns2); rx_shfl(X, Y, 1, c2, s2, ns2);
        RXC(13, c2, s2, ns2); rx_shfl(X, Y, 2, c2, s2, ns2);

        // ======== step ts+1 (layout B start) ========
        zz_apply(X, Y, zz, idxB, DZB, 0xC04);
        RXC(9,  c2, s2, ns2); rx_local(X, Y, 0, c2, s2, ns2);
        RXC(10, c2, s2, ns2); rx_local(X, Y, 1, c2, s2, ns2);
        RXC(11, c2, s2, ns2); rx_pack(X, Y, c2, s2, ns2);
        RXC(12, c2, s2, ns2); rx_shfl(X, Y, 1,  c2, s2, ns2);
        RXC(13, c2, s2, ns2); rx_shfl(X, Y, 2,  c2, s2, ns2);
        RXC(4,  c2, s2, ns2); rx_shfl(X, Y, 4,  c2, s2, ns2);
        RXC(5,  c2, s2, ns2); rx_shfl(X, Y, 8,  c2, s2, ns2);
        RXC(6,  c2, s2, ns2); rx_shfl(X, Y, 16, c2, s2, ns2);
        // ---- transpose B -> A ----
        __syncthreads();
        #pragma unroll
        for (int p1 = 0; p1 < 2; p1++)
        #pragma unroll
        for (int p0 = 0; p0 < 2; p0++) {
            int prl = p0 | (p1 << 1), prh = prl | 4;
            float2 xl = up(X[prl]), yl = up(Y[prl]), xh = up(X[prh]), yh = up(Y[prh]);
            int m0 = mB | (p0 << 8) | (p1 << 9);
            buf4[swz13(m0)]             = make_float4(xl.x, yl.x, xh.x, yh.x);
            buf4[swz13(m0 | (1 << 10))] = make_float4(xl.y, yl.y, xh.y, yh.y);
        }
        __syncthreads();
        #pragma unroll
        for (int pq = 0; pq < 4; pq++) {
            float4 v0 = buf4[swz13((t << 3) | pq)];
            float4 v1 = buf4[swz13((t << 3) | (1 << 2) | pq)];
            int p = 2 * pq;
            X[p]     = pk(v0.x, v1.x); Y[p]     = pk(v0.y, v1.y);
            X[p + 1] = pk(v0.z, v1.z); Y[p + 1] = pk(v0.w, v1.w);
        }
        RXC(0, c2, s2, ns2); rx_local(X, Y, 0, c2, s2, ns2);
        RXC(1, c2, s2, ns2); rx_local(X, Y, 1, c2, s2, ns2);
        RXC(2, c2, s2, ns2); rx_local(X, Y, 2, c2, s2, ns2);
        RXC(3, c2, s2, ns2); rx_pack(X, Y, c2, s2, ns2);
        RXC(7, c2, s2, ns2); rx_shfl(X, Y, 8,  c2, s2, ns2);
        RXC(8, c2, s2, ns2); rx_shfl(X, Y, 16, c2, s2, ns2);
    }
    // final state in layout A

    // ---- epilogue: store state (A pattern), compute 42 constants ----
    __syncthreads();
    #pragma unroll
    for (int h = 0; h < 2; h++)
    #pragma unroll
    for (int pq = 0; pq < 4; pq++) {
        int p = 2 * pq;
        float2 xa = up(X[p]), ya = up(Y[p]), xb = up(X[p + 1]), yb = up(Y[p + 1]);
        float4 v = h ? make_float4(xa.y, ya.y, xb.y, yb.y)
                     : make_float4(xa.x, ya.x, xb.x, yb.x);
        buf4[swz13((t << 3) | (h << 2) | pq)] = v;
    }
    __syncthreads();

    float tot = 0.f;
    #pragma unroll
    for (int pr = 0; pr < 8; pr++) {
        float2 x = up(X[pr]), y = up(Y[pr]);
        tot += x.x * x.x + x.y * x.y + y.x * y.x + y.y * y.y;
    }

    for (int q = 0; q < NQ; q++) {
        float cr = 0.f, ci = 0.f, zv = 0.f;
        if (q < 3) {
            #pragma unroll
            for (int pr = 0; pr < 8; pr++) {
                float2 x = up(X[pr]), y = up(Y[pr]);
                float n2 = x.x * x.x + x.y * x.y + y.x * y.x + y.y * y.y;
                zv += ((pr >> q) & 1) ? -n2 : n2;
            }
            #pragma unroll
            for (int pr = 0; pr < 8; pr++) if (!(pr & (1 << q))) {
                int e1 = pr | (1 << q);
                float2 xa = up(X[pr]), ya = up(Y[pr]);
                float2 xb = up(X[e1]), yb = up(Y[e1]);
                cr += xa.x * xb.x + ya.x * yb.x + xa.y * xb.y + ya.y * yb.y;
                ci += xa.x * yb.x - ya.x * xb.x + xa.y * yb.y - ya.y * xb.y;
            }
        } else if (q == 3) {
            #pragma unroll
            for (int pr = 0; pr < 8; pr++) {
                float2 x = up(X[pr]), y = up(Y[pr]);
                cr += x.x * x.y + y.x * y.y;
                ci += x.x * y.y - y.x * x.y;
                zv += x.x * x.x + y.x * y.x - x.y * x.y - y.y * y.y;
            }
        } else if (q < 9) {
            int msk = 1 << (q - 4);
            int mybit = (t >> (q - 4)) & 1;
            #pragma unroll
            for (int pr = 0; pr < 8; pr++) {
                u64 Xo = shflx(X[pr], msk), Yo = shflx(Y[pr], msk);
                if (!mybit) {
                    float2 x = up(X[pr]), y = up(Y[pr]);
                    float2 xo = up(Xo), yo = up(Yo);
                    cr += x.x * xo.x + y.x * yo.x + x.y * xo.y + y.y * yo.y;
                    ci += x.x * yo.x - y.x * xo.x + x.y * yo.y - y.y * xo.y;
                }
            }
            zv = mybit ? -tot : tot;
        } else {
            int mybit = (t >> (q - 4)) & 1;
            int mflip = 1 << (q - 1);        // m bit (q-1) = k_q for q>=9
            if (!mybit) {
                #pragma unroll
                for (int h = 0; h < 2; h++)
                #pragma unroll
                for (int pq = 0; pq < 4; pq++) {
                    float4 o = buf4[swz13(((t << 3) | (h << 2) | pq) ^ mflip)];
                    int p = 2 * pq;
                    float2 x0 = up(X[p]), y0 = up(Y[p]), x1 = up(X[p + 1]), y1 = up(Y[p + 1]);
                    float a0 = h ? x0.y : x0.x, b0 = h ? y0.y : y0.x;
                    float a1 = h ? x1.y : x1.x, b1 = h ? y1.y : y1.x;
                    cr += a0 * o.x + b0 * o.y + a1 * o.z + b1 * o.w;
                    ci += a0 * o.y - b0 * o.x + a1 * o.w - b1 * o.z;
                }
            }
            zv = mybit ? -tot : tot;
        }
        #pragma unroll
        for (int o = 16; o > 0; o >>= 1) {
            cr += __shfl_down_sync(0xffffffffu, cr, o);
            ci += __shfl_down_sync(0xffffffffu, ci, o);
            zv += __shfl_down_sync(0xffffffffu, zv, o);
        }
        if (lane == 0) {
            int i3 = 3 * (13 - q);
            warpacc[(i3 + 0) * 32 + wrp] = cr;
            warpacc[(i3 + 1) * 32 + wrp] = ci;
            warpacc[(i3 + 2) * 32 + wrp] = zv;
        }
    }
    __syncthreads();
    if (t < 42) {
        float s = 0.f;
        #pragma unroll
        for (int w = 0; w < 32; w++) s += warpacc[t * 32 + w];
        if ((t % 3) != 2) s *= 2.f;
        g_const[t] = s;
    }
}

__global__ __launch_bounds__(256)
void batch_kernel(const float* __restrict__ x, float* __restrict__ out)
{
    __shared__ float cst[48];
    int tid = threadIdx.x;
    if (tid < 42) cst[tid] = g_const[tid];
    __syncthreads();

    int tt = blockIdx.x * 256 + tid;
    int b = tt >> 4, i = tt & 15;
    if (i < NQ) {
        int q = 13 - i;
        float xv = x[b * NQ + q];
        float sn, cn;
        sincosf(xv, &sn, &cn);
        float R = cst[3 * i], I = cst[3 * i + 1];
        float* o = out + b * 42 + 3 * i;
        o[0] = R * cn - I * sn;
        o[1] = R * sn + I * cn;
        o[2] = cst[3 * i + 2];
    }
}

extern "C" void kernel_launch(void* const* d_in, const int* in_sizes, int n_in,
                              void* d_out, int out_size)
{
    const float* x = nullptr;
    const float* J = nullptr;
    const float* g = nullptr;
    for (int i = 0; i < n_in; i++) {
        if (in_sizes[i] == BATCH * NQ)  x = (const float*)d_in[i];
        else if (in_sizes[i] == NQ - 1) J = (const float*)d_in[i];
        else if (in_sizes[i] == NQ)     g = (const float*)d_in[i];
    }
    if (!x) x = (const float*)d_in[0];
    if (!J) J = (const float*)d_in[1];
    if (!g) g = (const float*)d_in[2];
    float* out = (float*)d_out;

    cudaFuncSetAttribute(evolve_kernel,
                         cudaFuncAttributeMaxDynamicSharedMemorySize, DYN_SMEM);

    evolve_kernel<<<1, NTHR, DYN_SMEM>>>(J, g);
    batch_kernel<<<BATCH * 16 / 256, 256>>>(x, out);
}

// round 6
// speedup vs baseline: 1.0003x; 1.0003x over previous
#include <cuda_runtime.h>
#include <math.h>

#define NQ    14
#define DIM   16384
#define NT    10
#define BATCH 2048
#define NTHR  1024
#define ZZN   8192
// dyn smem: buf4 (8192 * 16B = 128KB) + zz (8192 * 8B = 64KB) = 192KB
#define DYN_SMEM (ZZN * 16 + ZZN * 8)

typedef unsigned long long u64;

__device__ float g_const[48];

// ---- packed f32x2 helpers ----
__device__ __forceinline__ u64 f2mul(u64 a, u64 b) {
    u64 r; asm("mul.rn.f32x2 %0,%1,%2;" : "=l"(r) : "l"(a), "l"(b)); return r;
}
__device__ __forceinline__ u64 f2fma(u64 a, u64 b, u64 c) {
    u64 r; asm("fma.rn.f32x2 %0,%1,%2,%3;" : "=l"(r) : "l"(a), "l"(b), "l"(c)); return r;
}
__device__ __forceinline__ u64 pk(float lo, float hi) {
    u64 r; asm("mov.b64 %0,{%1,%2};" : "=l"(r) : "f"(lo), "f"(hi)); return r;
}
__device__ __forceinline__ float2 up(u64 d) {
    float lo, hi; asm("mov.b64 {%0,%1},%2;" : "=f"(lo), "=f"(hi) : "l"(d));
    return make_float2(lo, hi);
}
__device__ __forceinline__ u64 f2neg(u64 a) { return a ^ 0x8000000080000000ULL; }
__device__ __forceinline__ u64 f2swap(u64 a) { float2 t = up(a); return pk(t.y, t.x); }
__device__ __forceinline__ u64 shflx(u64 v, int m) { return __shfl_xor_sync(0xffffffffu, v, m); }

// transpose-buffer swizzle (16B units): conflict-free for both layouts
__device__ __forceinline__ int swz13(int m) { return m ^ ((m >> 3) & 7) ^ ((m >> 10) & 7); }

// ZZ-table scramble: GF(2)-linear, bank bits injective in both layouts
__device__ __forceinline__ int sigma13(int gm) {
    return ((gm >> 3) & 1)
         | (((gm >> 4) & 1) << 1)
         | ((((gm >> 5) ^ (gm >> 11)) & 1) << 2)
         | ((((gm >> 6) ^ (gm >> 12)) & 1) << 3)
         | ((gm & 7) << 4)
         | (((gm >> 7) & 0xF) << 7)
         | (((gm >> 11) & 3) << 11);
}

// ---- gate primitives on 8 packed pairs ----
__device__ __forceinline__ void rx_local(u64* X, u64* Y, int j, u64 c2, u64 s2, u64 ns2) {
    #pragma unroll
    for (int pr = 0; pr < 8; pr++) if (!(pr & (1 << j))) {
        int e1 = pr | (1 << j);
        u64 Xa = X[pr], Ya = Y[pr], Xb = X[e1], Yb = Y[e1];
        X[pr] = f2fma(c2, Xa, f2mul(s2, Yb));
        Y[pr] = f2fma(c2, Ya, f2mul(ns2, Xb));
        X[e1] = f2fma(c2, Xb, f2mul(s2, Ya));
        Y[e1] = f2fma(c2, Yb, f2mul(ns2, Xa));
    }
}
__device__ __forceinline__ void rx_pack(u64* X, u64* Y, u64 c2, u64 s2, u64 ns2) {
    #pragma unroll
    for (int pr = 0; pr < 8; pr++) {
        u64 Xs = f2swap(X[pr]), Ys = f2swap(Y[pr]);
        X[pr] = f2fma(c2, X[pr], f2mul(s2, Ys));
        Y[pr] = f2fma(c2, Y[pr], f2mul(ns2, Xs));
    }
}
__device__ __forceinline__ void rx_shfl(u64* X, u64* Y, int msk, u64 c2, u64 s2, u64 ns2) {
    #pragma unroll
    for (int pr = 0; pr < 8; pr++) {
        u64 Xo = shflx(X[pr], msk), Yo = shflx(Y[pr], msk);
        X[pr] = f2fma(c2, X[pr], f2mul(s2, Yo));
        Y[pr] = f2fma(c2, Y[pr], f2mul(ns2, Xo));
    }
}
__device__ __forceinline__ void zz_apply(u64* X, u64* Y, const float2* zz,
                                         int base, const int* D, int hiXor) {
    #pragma unroll
    for (int pr = 0; pr < 8; pr++) {
        int i = base ^ D[pr];
        float2 fl = zz[i], fh = zz[i ^ hiXor];
        u64 FX = pk(fl.x, fh.x), FY = pk(fl.y, fh.y);
        u64 Xo = X[pr], Yo = Y[pr];
        X[pr] = f2fma(FX, Xo, f2neg(f2mul(FY, Yo)));
        Y[pr] = f2fma(FX, Yo, f2mul(FY, Xo));
    }
}

// Layout A: k[2:0]=reg pr, k3=pack, k[8:4]=lane, k[13:9]=warp  (gates q0-q8)
// Layout B: pr = k9 | k10<<1 | k0<<2, pack=k11,
//           lane = {k12,k13,k4,k5,k6}, warp = {k7,k8,k1,k2,k3} (gates q9-q13, q4-q6)

__global__ __launch_bounds__(NTHR, 1)
void evolve_kernel(const float* __restrict__ J, const float* __restrict__ g)
{
    extern __shared__ char dynraw[];
    float4* buf4 = (float4*)dynraw;                // 8192 x 16B state transpose buffer
    float2* zz   = (float2*)(dynraw + ZZN * 16);   // 8192 diagonal factors (scrambled)

    __shared__ float2 rxcs[16];
    __shared__ float  Jsh[16];
    __shared__ float  warpacc[42 * 32];

    const int t    = threadIdx.x;
    const int lane = t & 31;
    const int wrp  = t >> 5;
    const float dt = 1.0f / (float)NT;

    if (t < NQ) {
        float h = 0.5f * g[t] * dt;
        float s, c; __sincosf(h, &s, &c);
        rxcs[t] = make_float2(c, s);
    }
    if (t < NQ - 1) Jsh[t] = J[t];
    __syncthreads();

    // ZZ table: mask m (13 Gray bits), D = sum J_i (1-2 m_i), store exp(-0.5 i dt D) at sigma(m)
    for (int m = t; m < ZZN; m += NTHR) {
        float D = 0.f;
        #pragma unroll
        for (int i = 0; i < NQ - 1; i++) {
            float Ji = Jsh[i];
            D += ((m >> i) & 1) ? -Ji : Ji;
        }
        float ang = -0.5f * dt * D;
        float s, c; __sincosf(ang, &s, &c);
        zz[sigma13(m)] = make_float2(c, s);
    }
    __syncthreads();

    u64 X[8], Y[8];
    #pragma unroll
    for (int pr = 0; pr < 8; pr++) { X[pr] = pk(0.0078125f, 0.0078125f); Y[pr] = 0ULL; }

    // ZZ per-pair constexpr deltas + base indices
    const int DZA[8] = {0x00, 0x10, 0x30, 0x20, 0x60, 0x70, 0x50, 0x40};   // sigma(gray(pr))
    const int DZB[8] = {0x000, 0x300, 0x600, 0x500, 0x010, 0x310, 0x610, 0x510};
    const int kA = t << 4;
    const int idxA = sigma13((kA ^ (kA >> 1)) & 0x1FFF);
    // B thread->m base: m_i = k_{i+1}
    const int mB = ((t >> 7) & 7) | (((t >> 2) & 7) << 3) | (((t >> 5) & 3) << 6)
                 | ((t & 3) << 11);
    const int kB = mB << 1;
    const int idxB = sigma13((kB ^ (kB >> 1)) & 0x1FFF);

    #define RXC(q, C2, S2, NS2) \
        { float2 _cs = rxcs[q]; C2 = pk(_cs.x, _cs.x); S2 = pk(_cs.y, _cs.y); NS2 = f2neg(S2); }

    for (int ts = 0; ts < NT; ts += 2) {
        u64 c2, s2, ns2;
        // ======== step ts (layout A start) ========
        zz_apply(X, Y, zz, idxA, DZA, 0x41);
        RXC(0, c2, s2, ns2); rx_local(X, Y, 0, c2, s2, ns2);
        RXC(1, c2, s2, ns2); rx_local(X, Y, 1, c2, s2, ns2);
        RXC(2, c2, s2, ns2); rx_local(X, Y, 2, c2, s2, ns2);
        RXC(3, c2, s2, ns2); rx_pack(X, Y, c2, s2, ns2);
        RXC(4, c2, s2, ns2); rx_shfl(X, Y, 1,  c2, s2, ns2);
        RXC(5, c2, s2, ns2); rx_shfl(X, Y, 2,  c2, s2, ns2);
        RXC(6, c2, s2, ns2); rx_shfl(X, Y, 4,  c2, s2, ns2);
        RXC(7, c2, s2, ns2); rx_shfl(X, Y, 8,  c2, s2, ns2);
        RXC(8, c2, s2, ns2); rx_shfl(X, Y, 16, c2, s2, ns2);
        // ---- transpose A -> B ----
        __syncthreads();
        #pragma unroll
        for (int h = 0; h < 2; h++)
        #pragma unroll
        for (int pq = 0; pq < 4; pq++) {
            int p = 2 * pq;
            float2 xa = up(X[p]), ya = up(Y[p]), xb = up(X[p + 1]), yb = up(Y[p + 1]);
            float4 v = h ? make_float4(xa.y, ya.y, xb.y, yb.y)
                         : make_float4(xa.x, ya.x, xb.x, yb.x);
            buf4[swz13((t << 3) | (h << 2) | pq)] = v;
        }
        __syncthreads();
        #pragma unroll
        for (int p1 = 0; p1 < 2; p1++)
        #pragma unroll
        for (int p0 = 0; p0 < 2; p0++) {
            int m0 = mB | (p0 << 8) | (p1 << 9);
            float4 v0 = buf4[swz13(m0)];
            float4 v1 = buf4[swz13(m0 | (1 << 10))];
            int prl = p0 | (p1 << 1), prh = prl | 4;
            X[prl] = pk(v0.x, v1.x); Y[prl] = pk(v0.y, v1.y);
            X[prh] = pk(v0.z, v1.z); Y[prh] = pk(v0.w, v1.w);
        }
        RXC(9,  c2, s2, ns2); rx_local(X, Y, 0, c2, s2, ns2);
        RXC(10, c2, s2, ns2); rx_local(X, Y, 1, c2, s2, ns2);
        RXC(11, c2, s2, ns2); rx_pack(X, Y, c2, s2, ns2);
        RXC(12, c2, s2, ns2); rx_shfl(X, Y, 1, c2, s2, ns2);
        RXC(13, c2, s2, ns2); rx_shfl(X, Y, 2, c2, s2, ns2);

        // ======== step ts+1 (layout B start) ========
        zz_apply(X, Y, zz, idxB, DZB, 0xC04);
        RXC(9,  c2, s2, ns2); rx_local(X, Y, 0, c2, s2, ns2);
        RXC(10, c2, s2, ns2); rx_local(X, Y, 1, c2, s2, ns2);
        RXC(11, c2, s2, ns2); rx_pack(X, Y, c2, s2, ns2);
        RXC(12, c2, s2, ns2); rx_shfl(X, Y, 1,  c2, s2, ns2);
        RXC(13, c2, s2, ns2); rx_shfl(X, Y, 2,  c2, s2, ns2);
        RXC(4,  c2, s2, ns2); rx_shfl(X, Y, 4,  c2, s2, ns2);
        RXC(5,  c2, s2, ns2); rx_shfl(X, Y, 8,  c2, s2, ns2);
        RXC(6,  c2, s2, ns2); rx_shfl(X, Y, 16, c2, s2, ns2);
        // ---- transpose B -> A ----
        __syncthreads();
        #pragma unroll
        for (int p1 = 0; p1 < 2; p1++)
        #pragma unroll
        for (int p0 = 0; p0 < 2; p0++) {
            int prl = p0 | (p1 << 1), prh = prl | 4;
            float2 xl = up(X[prl]), yl = up(Y[prl]), xh = up(X[prh]), yh = up(Y[prh]);
            int m0 = mB | (p0 << 8) | (p1 << 9);
            buf4[swz13(m0)]             = make_float4(xl.x, yl.x, xh.x, yh.x);
            buf4[swz13(m0 | (1 << 10))] = make_float4(xl.y, yl.y, xh.y, yh.y);
        }
        __syncthreads();
        #pragma unroll
        for (int pq = 0; pq < 4; pq++) {
            float4 v0 = buf4[swz13((t << 3) | pq)];
            float4 v1 = buf4[swz13((t << 3) | (1 << 2) | pq)];
            int p = 2 * pq;
            X[p]     = pk(v0.x, v1.x); Y[p]     = pk(v0.y, v1.y);
            X[p + 1] = pk(v0.z, v1.z); Y[p + 1] = pk(v0.w, v1.w);
        }
        RXC(0, c2, s2, ns2); rx_local(X, Y, 0, c2, s2, ns2);
        RXC(1, c2, s2, ns2); rx_local(X, Y, 1, c2, s2, ns2);
        RXC(2, c2, s2, ns2); rx_local(X, Y, 2, c2, s2, ns2);
        RXC(3, c2, s2, ns2); rx_pack(X, Y, c2, s2, ns2);
        RXC(7, c2, s2, ns2); rx_shfl(X, Y, 8,  c2, s2, ns2);
        RXC(8, c2, s2, ns2); rx_shfl(X, Y, 16, c2, s2, ns2);
    }
    // final state in layout A

    // ---- epilogue: store state (A pattern), compute 42 constants ----
    __syncthreads();
    #pragma unroll
    for (int h = 0; h < 2; h++)
    #pragma unroll
    for (int pq = 0; pq < 4; pq++) {
        int p = 2 * pq;
        float2 xa = up(X[p]), ya = up(Y[p]), xb = up(X[p + 1]), yb = up(Y[p + 1]);
        float4 v = h ? make_float4(xa.y, ya.y, xb.y, yb.y)
                     : make_float4(xa.x, ya.x, xb.x, yb.x);
        buf4[swz13((t << 3) | (h << 2) | pq)] = v;
    }
    __syncthreads();

    float tot = 0.f;
    #pragma unroll
    for (int pr = 0; pr < 8; pr++) {
        float2 x = up(X[pr]), y = up(Y[pr]);
        tot += x.x * x.x + x.y * x.y + y.x * y.x + y.y * y.y;
    }

    for (int q = 0; q < NQ; q++) {
        float cr = 0.f, ci = 0.f, zv = 0.f;
        if (q < 3) {
            #pragma unroll
            for (int pr = 0; pr < 8; pr++) {
                float2 x = up(X[pr]), y = up(Y[pr]);
                float n2 = x.x * x.x + x.y * x.y + y.x * y.x + y.y * y.y;
                zv += ((pr >> q) & 1) ? -n2 : n2;
            }
            #pragma unroll
            for (int pr = 0; pr < 8; pr++) if (!(pr & (1 << q))) {
                int e1 = pr | (1 << q);
                float2 xa = up(X[pr]), ya = up(Y[pr]);
                float2 xb = up(X[e1]), yb = up(Y[e1]);
                cr += xa.x * xb.x + ya.x * yb.x + xa.y * xb.y + ya.y * yb.y;
                ci += xa.x * yb.x - ya.x * xb.x + xa.y * yb.y - ya.y * xb.y;
            }
        } else if (q == 3) {
            #pragma unroll
            for (int pr = 0; pr < 8; pr++) {
                float2 x = up(X[pr]), y = up(Y[pr]);
                cr += x.x * x.y + y.x * y.y;
                ci += x.x * y.y - y.x * x.y;
                zv += x.x * x.x + y.x * y.x - x.y * x.y - y.y * y.y;
            }
        } else if (q < 9) {
            int msk = 1 << (q - 4);
            int mybit = (t >> (q - 4)) & 1;
            #pragma unroll
            for (int pr = 0; pr < 8; pr++) {
                u64 Xo = shflx(X[pr], msk), Yo = shflx(Y[pr], msk);
                if (!mybit) {
                    float2 x = up(X[pr]), y = up(Y[pr]);
                    float2 xo = up(Xo), yo = up(Yo);
                    cr += x.x * xo.x + y.x * yo.x + x.y * xo.y + y.y * yo.y;
                    ci += x.x * yo.x - y.x * xo.x + x.y * yo.y - y.y * xo.y;
                }
            }
            zv = mybit ? -tot : tot;
        } else {
            int mybit = (t >> (q - 4)) & 1;
            int mflip = 1 << (q - 1);        // m bit (q-1) = k_q for q>=9
            if (!mybit) {
                #pragma unroll
                for (int h = 0; h < 2; h++)
                #pragma unroll
                for (int pq = 0; pq < 4; pq++) {
                    float4 o = buf4[swz13(((t << 3) | (h << 2) | pq) ^ mflip)];
                    int p = 2 * pq;
                    float2 x0 = up(X[p]), y0 = up(Y[p]), x1 = up(X[p + 1]), y1 = up(Y[p + 1]);
                    float a0 = h ? x0.y : x0.x, b0 = h ? y0.y : y0.x;
                    float a1 = h ? x1.y : x1.x, b1 = h ? y1.y : y1.x;
                    cr += a0 * o.x + b0 * o.y + a1 * o.z + b1 * o.w;
                    ci += a0 * o.y - b0 * o.x + a1 * o.w - b1 * o.z;
                }
            }
            zv = mybit ? -tot : tot;
        }
        #pragma unroll
        for (int o = 16; o > 0; o >>= 1) {
            cr += __shfl_down_sync(0xffffffffu, cr, o);
            ci += __shfl_down_sync(0xffffffffu, ci, o);
            zv += __shfl_down_sync(0xffffffffu, zv, o);
        }
        if (lane == 0) {
            int i3 = 3 * (13 - q);
            warpacc[(i3 + 0) * 32 + wrp] = cr;
            warpacc[(i3 + 1) * 32 + wrp] = ci;
            warpacc[(i3 + 2) * 32 + wrp] = zv;
        }
    }
    __syncthreads();
    if (t < 42) {
        float s = 0.f;
        #pragma unroll
        for (int w = 0; w < 32; w++) s += warpacc[t * 32 + w];
        if ((t % 3) != 2) s *= 2.f;
        g_const[t] = s;
    }
}

__global__ __launch_bounds__(256)
void batch_kernel(const float* __restrict__ x, float* __restrict__ out)
{
    __shared__ float cst[48];
    int tid = threadIdx.x;
    if (tid < 42) cst[tid] = g_const[tid];
    __syncthreads();

    int tt = blockIdx.x * 256 + tid;
    int b = tt >> 4, i = tt & 15;
    if (i < NQ) {
        int q = 13 - i;
        float xv = x[b * NQ + q];
        float sn, cn;
        sincosf(xv, &sn, &cn);
        float R = cst[3 * i], I = cst[3 * i + 1];
        float* o = out + b * 42 + 3 * i;
        o[0] = R * cn - I * sn;
        o[1] = R * sn + I * cn;
        o[2] = cst[3 * i + 2];
    }
}

extern "C" void kernel_launch(void* const* d_in, const int* in_sizes, int n_in,
                              void* d_out, int out_size)
{
    const float* x = nullptr;
    const float* J = nullptr;
    const float* g = nullptr;
    for (int i = 0; i < n_in; i++) {
        if (in_sizes[i] == BATCH * NQ)  x = (const float*)d_in[i];
        else if (in_sizes[i] == NQ - 1) J = (const float*)d_in[i];
        else if (in_sizes[i] == NQ)     g = (const float*)d_in[i];
    }
    if (!x) x = (const float*)d_in[0];
    if (!J) J = (const float*)d_in[1];
    if (!g) g = (const float*)d_in[2];
    float* out = (float*)d_out;

    cudaFuncSetAttribute(evolve_kernel,
                         cudaFuncAttributeMaxDynamicSharedMemorySize, DYN_SMEM);

    evolve_kernel<<<1, NTHR, DYN_SMEM>>>(J, g);
    batch_kernel<<<BATCH * 16 / 256, 256>>>(x, out);
}

// round 7
// speedup vs baseline: 1.0064x; 1.0061x over previous
#include <cuda_runtime.h>
#include <math.h>

#define NQ    14
#define DIM   16384
#define NT    10
#define BATCH 2048
#define NTHR  1024
#define ZZN   8192
// dyn smem: buf4 (8192 * 16B = 128KB) + zz (8192 * 8B = 64KB) = 192KB
#define DYN_SMEM (ZZN * 16 + ZZN * 8)

typedef unsigned long long u64;

__device__ float g_const[48];

// ---- packed f32x2 helpers ----
__device__ __forceinline__ u64 f2mul(u64 a, u64 b) {
    u64 r; asm("mul.rn.f32x2 %0,%1,%2;" : "=l"(r) : "l"(a), "l"(b)); return r;
}
__device__ __forceinline__ u64 f2fma(u64 a, u64 b, u64 c) {
    u64 r; asm("fma.rn.f32x2 %0,%1,%2,%3;" : "=l"(r) : "l"(a), "l"(b), "l"(c)); return r;
}
__device__ __forceinline__ u64 pk(float lo, float hi) {
    u64 r; asm("mov.b64 %0,{%1,%2};" : "=l"(r) : "f"(lo), "f"(hi)); return r;
}
__device__ __forceinline__ float2 up(u64 d) {
    float lo, hi; asm("mov.b64 {%0,%1},%2;" : "=f"(lo), "=f"(hi) : "l"(d));
    return make_float2(lo, hi);
}
__device__ __forceinline__ u64 f2neg(u64 a) { return a ^ 0x8000000080000000ULL; }
__device__ __forceinline__ u64 f2swap(u64 a) { float2 t = up(a); return pk(t.y, t.x); }
__device__ __forceinline__ u64 shflx(u64 v, int m) { return __shfl_xor_sync(0xffffffffu, v, m); }

// transpose-buffer swizzle (16B units): conflict-free for both layouts
__device__ __forceinline__ int swz13(int m) { return m ^ ((m >> 3) & 7) ^ ((m >> 10) & 7); }

// ZZ-table scramble: GF(2)-linear, bank bits injective in both layouts
__device__ __forceinline__ int sigma13(int gm) {
    return ((gm >> 3) & 1)
         | (((gm >> 4) & 1) << 1)
         | ((((gm >> 5) ^ (gm >> 11)) & 1) << 2)
         | ((((gm >> 6) ^ (gm >> 12)) & 1) << 3)
         | ((gm & 7) << 4)
         | (((gm >> 7) & 0xF) << 7)
         | (((gm >> 11) & 3) << 11);
}

// ---- gate primitives on 8 packed pairs ----
__device__ __forceinline__ void rx_local(u64* X, u64* Y, int j, u64 c2, u64 s2, u64 ns2) {
    #pragma unroll
    for (int pr = 0; pr < 8; pr++) if (!(pr & (1 << j))) {
        int e1 = pr | (1 << j);
        u64 Xa = X[pr], Ya = Y[pr], Xb = X[e1], Yb = Y[e1];
        X[pr] = f2fma(c2, Xa, f2mul(s2, Yb));
        Y[pr] = f2fma(c2, Ya, f2mul(ns2, Xb));
        X[e1] = f2fma(c2, Xb, f2mul(s2, Ya));
        Y[e1] = f2fma(c2, Yb, f2mul(ns2, Xa));
    }
}
__device__ __forceinline__ void rx_pack(u64* X, u64* Y, u64 c2, u64 s2, u64 ns2) {
    #pragma unroll
    for (int pr = 0; pr < 8; pr++) {
        u64 Xs = f2swap(X[pr]), Ys = f2swap(Y[pr]);
        X[pr] = f2fma(c2, X[pr], f2mul(s2, Ys));
        Y[pr] = f2fma(c2, Y[pr], f2mul(ns2, Xs));
    }
}
__device__ __forceinline__ void rx_shfl(u64* X, u64* Y, int msk, u64 c2, u64 s2, u64 ns2) {
    #pragma unroll
    for (int pr = 0; pr < 8; pr++) {
        u64 Xo = shflx(X[pr], msk), Yo = shflx(Y[pr], msk);
        X[pr] = f2fma(c2, X[pr], f2mul(s2, Yo));
        Y[pr] = f2fma(c2, Y[pr], f2mul(ns2, Xo));
    }
}
__device__ __forceinline__ void zz_apply(u64* X, u64* Y, const float2* zz,
                                         int base, const int* D, int hiXor) {
    #pragma unroll
    for (int pr = 0; pr < 8; pr++) {
        int i = base ^ D[pr];
        float2 fl = zz[i], fh = zz[i ^ hiXor];
        u64 FX = pk(fl.x, fh.x), FY = pk(fl.y, fh.y);
        u64 Xo = X[pr], Yo = Y[pr];
        X[pr] = f2fma(FX, Xo, f2neg(f2mul(FY, Yo)));
        Y[pr] = f2fma(FX, Yo, f2mul(FY, Xo));
    }
}

// Layout A: k[2:0]=reg pr, k3=pack, k[8:4]=lane, k[13:9]=warp  (gates q0-q8)
// Layout B: pr = k9 | k10<<1 | k0<<2, pack=k11,
//           lane = {k12,k13,k4,k5,k6}, warp = {k7,k8,k1,k2,k3} (gates q9-q13, q4-q6)

__global__ __launch_bounds__(NTHR, 1)
void evolve_kernel(const float* __restrict__ J, const float* __restrict__ g)
{
    extern __shared__ char dynraw[];
    float4* buf4 = (float4*)dynraw;                // 8192 x 16B state transpose buffer
    float2* zz   = (float2*)(dynraw + ZZN * 16);   // 8192 diagonal factors (scrambled)

    __shared__ float2 rxcs[16];
    __shared__ float  Jsh[16];
    __shared__ float  warpacc[42 * 32];

    const int t    = threadIdx.x;
    const int lane = t & 31;
    const int wrp  = t >> 5;
    const float dt = 1.0f / (float)NT;

    if (t < NQ) {
        float h = 0.5f * g[t] * dt;
        float s, c; __sincosf(h, &s, &c);
        rxcs[t] = make_float2(c, s);
    }
    if (t < NQ - 1) Jsh[t] = J[t];
    __syncthreads();

    // ZZ table: mask m (13 Gray bits), D = sum J_i (1-2 m_i), store exp(-0.5 i dt D) at sigma(m)
    for (int m = t; m < ZZN; m += NTHR) {
        float D = 0.f;
        #pragma unroll
        for (int i = 0; i < NQ - 1; i++) {
            float Ji = Jsh[i];
            D += ((m >> i) & 1) ? -Ji : Ji;
        }
        float ang = -0.5f * dt * D;
        float s, c; __sincosf(ang, &s, &c);
        zz[sigma13(m)] = make_float2(c, s);
    }
    __syncthreads();

    u64 X[8], Y[8];
    #pragma unroll
    for (int pr = 0; pr < 8; pr++) { X[pr] = pk(0.0078125f, 0.0078125f); Y[pr] = 0ULL; }

    // ZZ per-pair constexpr deltas + base indices
    const int DZA[8] = {0x00, 0x10, 0x30, 0x20, 0x60, 0x70, 0x50, 0x40};   // sigma(gray(pr))
    const int DZB[8] = {0x000, 0x300, 0x600, 0x500, 0x010, 0x310, 0x610, 0x510};
    const int kA = t << 4;
    const int idxA = sigma13((kA ^ (kA >> 1)) & 0x1FFF);
    // B thread->m base: m_i = k_{i+1}
    const int mB = ((t >> 7) & 7) | (((t >> 2) & 7) << 3) | (((t >> 5) & 3) << 6)
                 | ((t & 3) << 11);
    const int kB = mB << 1;
    const int idxB = sigma13((kB ^ (kB >> 1)) & 0x1FFF);

    #define RXC(q, C2, S2, NS2) \
        { float2 _cs = rxcs[q]; C2 = pk(_cs.x, _cs.x); S2 = pk(_cs.y, _cs.y); NS2 = f2neg(S2); }

    for (int ts = 0; ts < NT; ts += 2) {
        u64 c2, s2, ns2;
        // ======== step ts (layout A start) ========
        zz_apply(X, Y, zz, idxA, DZA, 0x41);
        RXC(0, c2, s2, ns2); rx_local(X, Y, 0, c2, s2, ns2);
        RXC(1, c2, s2, ns2); rx_local(X, Y, 1, c2, s2, ns2);
        RXC(2, c2, s2, ns2); rx_local(X, Y, 2, c2, s2, ns2);
        RXC(3, c2, s2, ns2); rx_pack(X, Y, c2, s2, ns2);
        RXC(4, c2, s2, ns2); rx_shfl(X, Y, 1,  c2, s2, ns2);
        RXC(5, c2, s2, ns2); rx_shfl(X, Y, 2,  c2, s2, ns2);
        RXC(6, c2, s2, ns2); rx_shfl(X, Y, 4,  c2, s2, ns2);
        RXC(7, c2, s2, ns2); rx_shfl(X, Y, 8,  c2, s2, ns2);
        RXC(8, c2, s2, ns2); rx_shfl(X, Y, 16, c2, s2, ns2);
        // ---- transpose A -> B ----
        __syncthreads();
        #pragma unroll
        for (int h = 0; h < 2; h++)
        #pragma unroll
        for (int pq = 0; pq < 4; pq++) {
            int p = 2 * pq;
            float2 xa = up(X[p]), ya = up(Y[p]), xb = up(X[p + 1]), yb = up(Y[p + 1]);
            float4 v = h ? make_float4(xa.y, ya.y, xb.y, yb.y)
                         : make_float4(xa.x, ya.x, xb.x, yb.x);
            buf4[swz13((t << 3) | (h << 2) | pq)] = v;
        }
        __syncthreads();
        #pragma unroll
        for (int p1 = 0; p1 < 2; p1++)
        #pragma unroll
        for (int p0 = 0; p0 < 2; p0++) {
            int m0 = mB | (p0 << 8) | (p1 << 9);
            float4 v0 = buf4[swz13(m0)];
            float4 v1 = buf4[swz13(m0 | (1 << 10))];
            int prl = p0 | (p1 << 1), prh = prl | 4;
            X[prl] = pk(v0.x, v1.x); Y[prl] = pk(v0.y, v1.y);
            X[prh] = pk(v0.z, v1.z); Y[prh] = pk(v0.w, v1.w);
        }
        RXC(9,  c2, s2, ns2); rx_local(X, Y, 0, c2, s2, ns2);
        RXC(10, c2, s2, ns2); rx_local(X, Y, 1, c2, s2, ns2);
        RXC(11, c2, s2, ns2); rx_pack(X, Y, c2, s2, ns2);
        RXC(12, c2, s2, ns2); rx_shfl(X, Y, 1, c2, s2, ns2);
        RXC(13, c2, s2, ns2); rx_shfl(X, Y, 2, c2, s2, ns2);

        // ======== step ts+1 (layout B start) ========
        zz_apply(X, Y, zz, idxB, DZB, 0xC04);
        RXC(9,  c2, s2, ns2); rx_local(X, Y, 0, c2, s2, ns2);
        RXC(10, c2, s2, ns2); rx_local(X, Y, 1, c2, s2, ns2);
        RXC(11, c2, s2, ns2); rx_pack(X, Y, c2, s2, ns2);
        RXC(12, c2, s2, ns2); rx_shfl(X, Y, 1,  c2, s2, ns2);
        RXC(13, c2, s2, ns2); rx_shfl(X, Y, 2,  c2, s2, ns2);
        RXC(4,  c2, s2, ns2); rx_shfl(X, Y, 4,  c2, s2, ns2);
        RXC(5,  c2, s2, ns2); rx_shfl(X, Y, 8,  c2, s2, ns2);
        RXC(6,  c2, s2, ns2); rx_shfl(X, Y, 16, c2, s2, ns2);
        // ---- transpose B -> A ----
        __syncthreads();
        #pragma unroll
        for (int p1 = 0; p1 < 2; p1++)
        #pragma unroll
        for (int p0 = 0; p0 < 2; p0++) {
            int prl = p0 | (p1 << 1), prh = prl | 4;
            float2 xl = up(X[prl]), yl = up(Y[prl]), xh = up(X[prh]), yh = up(Y[prh]);
            int m0 = mB | (p0 << 8) | (p1 << 9);
            buf4[swz13(m0)]             = make_float4(xl.x, yl.x, xh.x, yh.x);
            buf4[swz13(m0 | (1 << 10))] = make_float4(xl.y, yl.y, xh.y, yh.y);
        }
        __syncthreads();
        #pragma unroll
        for (int pq = 0; pq < 4; pq++) {
            float4 v0 = buf4[swz13((t << 3) | pq)];
            float4 v1 = buf4[swz13((t << 3) | (1 << 2) | pq)];
            int p = 2 * pq;
            X[p]     = pk(v0.x, v1.x); Y[p]     = pk(v0.y, v1.y);
            X[p + 1] = pk(v0.z, v1.z); Y[p + 1] = pk(v0.w, v1.w);
        }
        RXC(0, c2, s2, ns2); rx_local(X, Y, 0, c2, s2, ns2);
        RXC(1, c2, s2, ns2); rx_local(X, Y, 1, c2, s2, ns2);
        RXC(2, c2, s2, ns2); rx_local(X, Y, 2, c2, s2, ns2);
        RXC(3, c2, s2, ns2); rx_pack(X, Y, c2, s2, ns2);
        RXC(7, c2, s2, ns2); rx_shfl(X, Y, 8,  c2, s2, ns2);
        RXC(8, c2, s2, ns2); rx_shfl(X, Y, 16, c2, s2, ns2);
    }
    // final state in layout A

    // ---- epilogue: store state (A pattern), compute 42 constants ----
    __syncthreads();
    #pragma unroll
    for (int h = 0; h < 2; h++)
    #pragma unroll
    for (int pq = 0; pq < 4; pq++) {
        int p = 2 * pq;
        float2 xa = up(X[p]), ya = up(Y[p]), xb = up(X[p + 1]), yb = up(Y[p + 1]);
        float4 v = h ? make_float4(xa.y, ya.y, xb.y, yb.y)
                     : make_float4(xa.x, ya.x, xb.x, yb.x);
        buf4[swz13((t << 3) | (h << 2) | pq)] = v;
    }
    __syncthreads();

    float tot = 0.f;
    #pragma unroll
    for (int pr = 0; pr < 8; pr++) {
        float2 x = up(X[pr]), y = up(Y[pr]);
        tot += x.x * x.x + x.y * x.y + y.x * y.x + y.y * y.y;
    }

    for (int q = 0; q < NQ; q++) {
        float cr = 0.f, ci = 0.f, zv = 0.f;
        if (q < 3) {
            #pragma unroll
            for (int pr = 0; pr < 8; pr++) {
                float2 x = up(X[pr]), y = up(Y[pr]);
                float n2 = x.x * x.x + x.y * x.y + y.x * y.x + y.y * y.y;
                zv += ((pr >> q) & 1) ? -n2 : n2;
            }
            #pragma unroll
            for (int pr = 0; pr < 8; pr++) if (!(pr & (1 << q))) {
                int e1 = pr | (1 << q);
                float2 xa = up(X[pr]), ya = up(Y[pr]);
                float2 xb = up(X[e1]), yb = up(Y[e1]);
                cr += xa.x * xb.x + ya.x * yb.x + xa.y * xb.y + ya.y * yb.y;
                ci += xa.x * yb.x - ya.x * xb.x + xa.y * yb.y - ya.y * xb.y;
            }
        } else if (q == 3) {
            #pragma unroll
            for (int pr = 0; pr < 8; pr++) {
                float2 x = up(X[pr]), y = up(Y[pr]);
                cr += x.x * x.y + y.x * y.y;
                ci += x.x * y.y - y.x * x.y;
                zv += x.x * x.x + y.x * y.x - x.y * x.y - y.y * y.y;
            }
        } else if (q < 9) {
            int msk = 1 << (q - 4);
            int mybit = (t >> (q - 4)) & 1;
            #pragma unroll
            for (int pr = 0; pr < 8; pr++) {
                u64 Xo = shflx(X[pr], msk), Yo = shflx(Y[pr], msk);
                if (!mybit) {
                    float2 x = up(X[pr]), y = up(Y[pr]);
                    float2 xo = up(Xo), yo = up(Yo);
                    cr += x.x * xo.x + y.x * yo.x + x.y * xo.y + y.y * yo.y;
                    ci += x.x * yo.x - y.x * xo.x + x.y * yo.y - y.y * xo.y;
                }
            }
            zv = mybit ? -tot : tot;
        } else {
            int mybit = (t >> (q - 4)) & 1;
            int mflip = 1 << (q - 1);        // m bit (q-1) = k_q for q>=9
            if (!mybit) {
                #pragma unroll
                for (int h = 0; h < 2; h++)
                #pragma unroll
                for (int pq = 0; pq < 4; pq++) {
                    float4 o = buf4[swz13(((t << 3) | (h << 2) | pq) ^ mflip)];
                    int p = 2 * pq;
                    float2 x0 = up(X[p]), y0 = up(Y[p]), x1 = up(X[p + 1]), y1 = up(Y[p + 1]);
                    float a0 = h ? x0.y : x0.x, b0 = h ? y0.y : y0.x;
                    float a1 = h ? x1.y : x1.x, b1 = h ? y1.y : y1.x;
                    cr += a0 * o.x + b0 * o.y + a1 * o.z + b1 * o.w;
                    ci += a0 * o.y - b0 * o.x + a1 * o.w - b1 * o.z;
                }
            }
            zv = mybit ? -tot : tot;
        }
        #pragma unroll
        for (int o = 16; o > 0; o >>= 1) {
            cr += __shfl_down_sync(0xffffffffu, cr, o);
            ci += __shfl_down_sync(0xffffffffu, ci, o);
            zv += __shfl_down_sync(0xffffffffu, zv, o);
        }
        if (lane == 0) {
            int i3 = 3 * (13 - q);
            warpacc[(i3 + 0) * 32 + wrp] = cr;
            warpacc[(i3 + 1) * 32 + wrp] = ci;
            warpacc[(i3 + 2) * 32 + wrp] = zv;
        }
    }
    __syncthreads();
    if (t < 42) {
        float s = 0.f;
        #pragma unroll
        for (int w = 0; w < 32; w++) s += warpacc[t * 32 + w];
        if ((t % 3) != 2) s *= 2.f;
        g_const[t] = s;
    }
}

__global__ __launch_bounds__(256)
void batch_kernel(const float* __restrict__ x, float* __restrict__ out)
{
    __shared__ float cst[48];
    int tid = threadIdx.x;
    if (tid < 42) cst[tid] = g_const[tid];
    __syncthreads();

    int tt = blockIdx.x * 256 + tid;
    int b = tt >> 4, i = tt & 15;
    if (i < NQ) {
        int q = 13 - i;
        float xv = x[b * NQ + q];
        float sn, cn;
        sincosf(xv, &sn, &cn);
        float R = cst[3 * i], I = cst[3 * i + 1];
        float* o = out + b * 42 + 3 * i;
        o[0] = R * cn - I * sn;
        o[1] = R * sn + I * cn;
        o[2] = cst[3 * i + 2];
    }
}

extern "C" void kernel_launch(void* const* d_in, const int* in_sizes, int n_in,
                              void* d_out, int out_size)
{
    const float* x = nullptr;
    const float* J = nullptr;
    const float* g = nullptr;
    for (int i = 0; i < n_in; i++) {
        if (in_sizes[i] == BATCH * NQ)  x = (const float*)d_in[i];
        else if (in_sizes[i] == NQ - 1) J = (const float*)d_in[i];
        else if (in_sizes[i] == NQ)     g = (const float*)d_in[i];
    }
    if (!x) x = (const float*)d_in[0];
    if (!J) J = (const float*)d_in[1];
    if (!g) g = (const float*)d_in[2];
    float* out = (float*)d_out;

    cudaFuncSetAttribute(evolve_kernel,
                         cudaFuncAttributeMaxDynamicSharedMemorySize, DYN_SMEM);

    evolve_kernel<<<1, NTHR, DYN_SMEM>>>(J, g);
    batch_kernel<<<BATCH * 16 / 256, 256>>>(x, out);
}